// round 2
// baseline (speedup 1.0000x reference)
#include <cuda_runtime.h>

namespace {
constexpr int Bsz    = 16384;
constexpr int Ncap   = 32;
constexpr int Din    = 128;
constexpr int Dout   = 256;
constexpr int RITERS = 3;
constexpr int UNITS  = Bsz / 2;

// shared memory layout (float offsets)
constexpr int OFF_W    = 0;                  // 32*16*32*2 = 32768 (W fragments, tf32)
constexpr int OFF_A    = OFF_W + 32768;      // 64 slots * 132 = 8448 (A fragments)
constexpr int OFF_BIAS = OFF_A + 8448;       // 256
constexpr int OFF_NRM  = OFF_BIAS + 256;     // [2][32][4] = 256
constexpr int OFF_AGR  = OFF_NRM + 256;      // [2][32][4] = 256
constexpr int OFF_SQ   = OFF_AGR + 256;      // [2][4] = 8
constexpr int OFF_V    = OFF_SQ + 8;         // [2][256] = 512
constexpr int SMEM_FLOATS = OFF_V + 512;
constexpr int SMEM_BYTES  = SMEM_FLOATS * 4; // ~170 KB
}

__device__ __forceinline__ float to_tf32(float x) {
    float y;
    asm("cvt.rna.tf32.f32 %0, %1;" : "=f"(y) : "f"(x));
    return y;
}

__device__ __forceinline__ void mma_tf32(float* c, const float4 a, const float2 b) {
    asm volatile(
        "mma.sync.aligned.m16n8k8.row.col.f32.tf32.tf32.f32 "
        "{%0,%1,%2,%3}, {%4,%5,%6,%7}, {%8,%9}, {%0,%1,%2,%3};\n"
        : "+f"(c[0]), "+f"(c[1]), "+f"(c[2]), "+f"(c[3])
        : "r"(__float_as_uint(a.x)), "r"(__float_as_uint(a.y)),
          "r"(__float_as_uint(a.z)), "r"(__float_as_uint(a.w)),
          "r"(__float_as_uint(b.x)), "r"(__float_as_uint(b.y)));
}

// Store one float4 of embeds (linear float4 index i in [0,2048)) into the
// fragment-permuted tf32 A layout.
__device__ __forceinline__ void stageA(float* sm, int i, float4 e) {
    int r    = i >> 5;              // row 0..63
    int j4   = i & 31;              // k-block of 4
    int rgA  = r >> 5;
    int mt   = (r >> 4) & 1;
    int rr   = r & 15;
    int ks   = j4 >> 1;
    int aidx = (rr >> 3) + ((j4 & 1) << 1);
    int slot = (rgA * 2 + mt) * 16 + ks;
    int base = OFF_A + slot * 132 + (rr & 7) * 16 + aidx;
    sm[base + 0]  = to_tf32(e.x);
    sm[base + 4]  = to_tf32(e.y);
    sm[base + 8]  = to_tf32(e.z);
    sm[base + 12] = to_tf32(e.w);
}

__global__ void __launch_bounds__(256, 1)
dyr_agg_kernel(const float* __restrict__ embeds,
               const float* __restrict__ weights,
               const float* __restrict__ Wg,
               const float* __restrict__ bg,
               float* __restrict__ out)
{
    extern __shared__ float sm[];
    const int tid  = threadIdx.x;
    const int lane = tid & 31;
    const int w    = tid >> 5;     // warp 0..7
    const int cg   = w & 3;        // column group: 64 cols at cg*64
    const int rg   = w >> 2;       // which batch of the pair
    const int qr   = lane >> 2;    // 0..7
    const int qc   = lane & 3;     // 0..3

    // ---- stage W into fragment-permuted tf32 layout (once per CTA) ----
    for (int idx = tid; idx < 32 * 16 * 32; idx += 256) {
        int nt = idx >> 9;
        int ks = (idx >> 5) & 15;
        int ln = idx & 31;
        int k0 = ks * 8 + (ln & 3);
        int n  = nt * 8 + (ln >> 2);
        sm[OFF_W + idx * 2 + 0] = to_tf32(Wg[k0 * Dout + n]);
        sm[OFF_W + idx * 2 + 1] = to_tf32(Wg[(k0 + 4) * Dout + n]);
    }
    if (tid < Dout) sm[OFF_BIAS + tid] = bg[tid];

    // ---- stage A for this CTA's first unit ----
    if (blockIdx.x < UNITS) {
        const float4* eg = (const float4*)(embeds + (size_t)blockIdx.x * 2 * Ncap * Din);
        #pragma unroll
        for (int t = 0; t < 8; t++) {
            int i = tid + t * 256;
            stageA(sm, i, eg[i]);
        }
    }
    __syncthreads();

    float* out_poses = out;
    float* out_c     = out + (size_t)Bsz * Dout;

    for (int unit = blockIdx.x; unit < UNITS; unit += gridDim.x) {
        const int  b0       = unit * 2;
        const int  nunit    = unit + gridDim.x;
        const bool has_next = nunit < UNITS;

        // ---- prefetch next unit's A into registers (latency hidden by GEMM) ----
        float4 pf[8];
        if (has_next) {
            const float4* eg = (const float4*)(embeds + (size_t)nunit * 2 * Ncap * Din);
            #pragma unroll
            for (int t = 0; t < 8; t++) pf[t] = eg[tid + t * 256];
        }
        // routing logits, register-resident (lane = capsule index n)
        float bij = weights[(size_t)(b0 + rg) * Ncap + lane];

        // ---- GEMM: each warp computes 32 rows (rg) x 64 cols (cg) ----
        float c[2][8][4];
        #pragma unroll
        for (int mt = 0; mt < 2; mt++)
            #pragma unroll
            for (int j = 0; j < 8; j++)
                #pragma unroll
                for (int q = 0; q < 4; q++) c[mt][j][q] = 0.0f;

        #pragma unroll
        for (int ks = 0; ks < 16; ks++) {
            float4 a0 = *(const float4*)&sm[OFF_A + ((rg * 2 + 0) * 16 + ks) * 132 + lane * 4];
            float4 a1 = *(const float4*)&sm[OFF_A + ((rg * 2 + 1) * 16 + ks) * 132 + lane * 4];
            #pragma unroll
            for (int j = 0; j < 8; j++) {
                float2 b = *(const float2*)&sm[OFF_W + (((cg * 8 + j) * 16 + ks) * 32 + lane) * 2];
                mma_tf32(c[0][j], a0, b);
                mma_tf32(c[1][j], a1, b);
            }
        }

        // ---- bias add + per-row squared-norm partials ----
        float pn[2][2] = {{0.f, 0.f}, {0.f, 0.f}};
        #pragma unroll
        for (int mt = 0; mt < 2; mt++)
            #pragma unroll
            for (int j = 0; j < 8; j++)
                #pragma unroll
                for (int q = 0; q < 4; q++) {
                    int p = q & 1, h = q >> 1;
                    int col = cg * 64 + j * 8 + qc * 2 + p;
                    float v = c[mt][j][q] + sm[OFF_BIAS + col];
                    c[mt][j][q] = v;
                    pn[mt][h] += v * v;
                }
        #pragma unroll
        for (int mt = 0; mt < 2; mt++)
            #pragma unroll
            for (int h = 0; h < 2; h++) {
                pn[mt][h] += __shfl_xor_sync(0xffffffffu, pn[mt][h], 1);
                pn[mt][h] += __shfl_xor_sync(0xffffffffu, pn[mt][h], 2);
            }
        if (qc == 0) {
            #pragma unroll
            for (int mt = 0; mt < 2; mt++)
                #pragma unroll
                for (int h = 0; h < 2; h++) {
                    int n = mt * 16 + qr + h * 8;
                    sm[OFF_NRM + rg * 128 + n * 4 + cg] = pn[mt][h];
                }
        }
        __syncthreads();  // [B1] GEMM reads of A done; norm partials visible

        // ---- store prefetched A into smem for the next unit ----
        if (has_next) {
            #pragma unroll
            for (int t = 0; t < 8; t++) stageA(sm, tid + t * 256, pf[t]);
        }

        // ---- normalize u_hat fragments (inv computed redundantly per thread) ----
        #pragma unroll
        for (int mt = 0; mt < 2; mt++)
            #pragma unroll
            for (int h = 0; h < 2; h++) {
                int n = mt * 16 + qr + h * 8;
                float4 p = *(const float4*)&sm[OFF_NRM + rg * 128 + n * 4];
                float s   = p.x + p.y + p.z + p.w;
                float inv = 1.0f / fmaxf(sqrtf(s), 1e-12f);
                #pragma unroll
                for (int j = 0; j < 8; j++) {
                    c[mt][j][2 * h + 0] *= inv;
                    c[mt][j][2 * h + 1] *= inv;
                }
            }

        // ---- dynamic routing: everything fragment/register-resident ----
        float cval = 0.0f;
        #pragma unroll
        for (int it = 0; it < RITERS; it++) {
            // softmax over this warp's rg (all warps, redundant -> no barrier)
            float m = bij;
            #pragma unroll
            for (int off = 16; off; off >>= 1)
                m = fmaxf(m, __shfl_xor_sync(0xffffffffu, m, off));
            float e = expf(bij - m);
            float ssum = e;
            #pragma unroll
            for (int off = 16; off; off >>= 1)
                ssum += __shfl_xor_sync(0xffffffffu, ssum, off);
            cval = e * (32.0f / ssum);

            float cv0 = __shfl_sync(0xffffffffu, cval, qr);
            float cv1 = __shfl_sync(0xffffffffu, cval, qr + 8);
            float cv2 = __shfl_sync(0xffffffffu, cval, qr + 16);
            float cv3 = __shfl_sync(0xffffffffu, cval, qr + 24);

            // s[d] partials from fragments, reduce over qr -> all lanes hold s
            float sp[8][2];
            #pragma unroll
            for (int j = 0; j < 8; j++) {
                sp[j][0] = cv0 * c[0][j][0] + cv1 * c[0][j][2]
                         + cv2 * c[1][j][0] + cv3 * c[1][j][2];
                sp[j][1] = cv0 * c[0][j][1] + cv1 * c[0][j][3]
                         + cv2 * c[1][j][1] + cv3 * c[1][j][3];
            }
            #pragma unroll
            for (int j = 0; j < 8; j++)
                #pragma unroll
                for (int p = 0; p < 2; p++) {
                    sp[j][p] += __shfl_xor_sync(0xffffffffu, sp[j][p], 4);
                    sp[j][p] += __shfl_xor_sync(0xffffffffu, sp[j][p], 8);
                    sp[j][p] += __shfl_xor_sync(0xffffffffu, sp[j][p], 16);
                }

            // warp-partial sum(s^2) over this warp's 64 cols
            float qs = 0.0f;
            #pragma unroll
            for (int j = 0; j < 8; j++)
                qs += sp[j][0] * sp[j][0] + sp[j][1] * sp[j][1];
            qs += __shfl_xor_sync(0xffffffffu, qs, 1);
            qs += __shfl_xor_sync(0xffffffffu, qs, 2);
            if (lane == 0) sm[OFF_SQ + rg * 4 + cg] = qs;
            __syncthreads();  // [B per iter]

            float t4 = sm[OFF_SQ + rg * 4 + 0] + sm[OFF_SQ + rg * 4 + 1]
                     + sm[OFF_SQ + rg * 4 + 2] + sm[OFF_SQ + rg * 4 + 3];
            float scale = t4 / ((1.0f + t4) * sqrtf(t4 + 1e-9f));

            if (it < RITERS - 1) {
                // agree[n] partials over this warp's 64 cols, from fragments
                float ap[2][2] = {{0.f, 0.f}, {0.f, 0.f}};
                #pragma unroll
                for (int j = 0; j < 8; j++) {
                    float s0 = sp[j][0], s1 = sp[j][1];
                    ap[0][0] += c[0][j][0] * s0 + c[0][j][1] * s1;
                    ap[0][1] += c[0][j][2] * s0 + c[0][j][3] * s1;
                    ap[1][0] += c[1][j][0] * s0 + c[1][j][1] * s1;
                    ap[1][1] += c[1][j][2] * s0 + c[1][j][3] * s1;
                }
                #pragma unroll
                for (int mt = 0; mt < 2; mt++)
                    #pragma unroll
                    for (int h = 0; h < 2; h++) {
                        float a = ap[mt][h] * scale;
                        a += __shfl_xor_sync(0xffffffffu, a, 1);
                        a += __shfl_xor_sync(0xffffffffu, a, 2);
                        if (qc == 0) {
                            int n = mt * 16 + qr + h * 8;
                            sm[OFF_AGR + rg * 128 + n * 4 + cg] = a;
                        }
                    }
                __syncthreads();  // agree partials visible
                float4 ag = *(const float4*)&sm[OFF_AGR + rg * 128 + lane * 4];
                bij += ag.x + ag.y + ag.z + ag.w;
            } else {
                // final iter: stage v into smem for coalesced output
                #pragma unroll
                for (int j = 0; j < 8; j++)
                    if (qr == j) {
                        float2 vv = make_float2(scale * sp[j][0], scale * sp[j][1]);
                        *(float2*)&sm[OFF_V + rg * 256 + cg * 64 + j * 8 + qc * 2] = vv;
                    }
                if (cg == 0)
                    out_c[(size_t)(b0 + rg) * Ncap + lane] = cval;
            }
        }

        __syncthreads();  // v staged; also protects A-prefetch stores vs next GEMM
        out_poses[(size_t)b0 * Dout + tid]       = sm[OFF_V + tid];
        out_poses[(size_t)(b0 + 1) * Dout + tid] = sm[OFF_V + 256 + tid];
    }
}

extern "C" void kernel_launch(void* const* d_in, const int* in_sizes, int n_in,
                              void* d_out, int out_size) {
    const float* embeds  = (const float*)d_in[0];
    const float* weights = (const float*)d_in[1];
    const float* Wg      = (const float*)d_in[2];
    const float* bg      = (const float*)d_in[3];
    float* out = (float*)d_out;

    cudaFuncSetAttribute(dyr_agg_kernel,
                         cudaFuncAttributeMaxDynamicSharedMemorySize, SMEM_BYTES);
    int sms = 148;
    cudaDeviceGetAttribute(&sms, cudaDevAttrMultiProcessorCount, 0);
    dyr_agg_kernel<<<sms, 256, SMEM_BYTES>>>(embeds, weights, Wg, bg, out);
}

// round 3
// speedup vs baseline: 1.7473x; 1.7473x over previous
#include <cuda_runtime.h>

namespace {
constexpr int Bsz    = 16384;
constexpr int Ncap   = 32;
constexpr int Din    = 128;
constexpr int Dout   = 256;
constexpr int RITERS = 3;
constexpr int UNITS  = Bsz / 2;

// shared memory layout (float offsets)
// W: 16 jp-groups * 16 ks * 32 lanes * float4 = 32768 floats (131072 B)
constexpr int OFF_W    = 0;
constexpr int OFF_A    = OFF_W + 32768;        // per-half: 64 slots * 132 = 8448 floats; x2
constexpr int OFF_BIAS = OFF_A + 2 * 8448;     // 256
constexpr int OFF_SCR  = OFF_BIAS + 256;       // per-half scratch, 1792 floats each
// scratch offsets within a half
constexpr int S_NRM = 0;      // [32][4] = 128 -> use 256 for 2 rgs? no: per-half has 2 batches
constexpr int S_INV = 256;    // 64
constexpr int S_BIJ = 320;    // 64
constexpr int S_C   = 384;    // 64
constexpr int S_S   = 448;    // [2][256] = 512
constexpr int S_V   = 960;    // 512
constexpr int S_SQP = 1472;   // 16
constexpr int S_SC  = 1488;   // 4
constexpr int S_AGR = 1492;   // [2][32][4] = 256
constexpr int SCR_SIZE = 1792;
constexpr int SMEM_FLOATS = OFF_SCR + 2 * SCR_SIZE;
constexpr int SMEM_BYTES  = SMEM_FLOATS * 4;   // ~212 KB
}

__device__ __forceinline__ float to_tf32(float x) {
    float y;
    asm("cvt.rna.tf32.f32 %0, %1;" : "=f"(y) : "f"(x));
    return y;
}

__device__ __forceinline__ void bar_half(int half) {
    asm volatile("bar.sync %0, 256;" :: "r"(1 + half) : "memory");
}

__device__ __forceinline__ void mma_tf32(float* c, const float4 a, float b0, float b1) {
    asm volatile(
        "mma.sync.aligned.m16n8k8.row.col.f32.tf32.tf32.f32 "
        "{%0,%1,%2,%3}, {%4,%5,%6,%7}, {%8,%9}, {%0,%1,%2,%3};\n"
        : "+f"(c[0]), "+f"(c[1]), "+f"(c[2]), "+f"(c[3])
        : "r"(__float_as_uint(a.x)), "r"(__float_as_uint(a.y)),
          "r"(__float_as_uint(a.z)), "r"(__float_as_uint(a.w)),
          "r"(__float_as_uint(b0)), "r"(__float_as_uint(b1)));
}

__global__ void __launch_bounds__(512, 1)
dyr_agg_kernel(const float* __restrict__ embeds,
               const float* __restrict__ weights,
               const float* __restrict__ Wg,
               const float* __restrict__ bg,
               float* __restrict__ out)
{
    extern __shared__ float sm[];
    const int tid  = threadIdx.x;
    const int half = tid >> 8;       // 0 or 1: independent 256-thread worker
    const int htid = tid & 255;
    const int lane = tid & 31;
    const int wh   = (tid >> 5) & 7; // warp-in-half 0..7
    const int cg   = wh & 3;         // column group: 64 cols at cg*64
    const int rg   = wh >> 2;        // which batch of the pair
    const int qr   = lane >> 2;      // 0..7
    const int qc   = lane & 3;       // 0..3

    float* scr = sm + OFF_SCR + half * SCR_SIZE;
    float* As  = sm + OFF_A + half * 8448;

    // ---- stage W (paired-j layout) + bias, whole CTA, once ----
    // slot (nt2, ks, ln): float4 = {W[k0][n0], W[k0+4][n0], W[k0][n1], W[k0+4][n1]}
    // where j0=2*nt2, n0=j0*8+(ln>>2), n1=n0+8, k0=ks*8+(ln&3)
    for (int idx = tid; idx < 16 * 16 * 32; idx += 512) {
        int nt2 = idx >> 9;
        int ks  = (idx >> 5) & 15;
        int ln  = idx & 31;
        int k0  = ks * 8 + (ln & 3);
        int n0  = nt2 * 16 + (ln >> 2);
        sm[OFF_W + idx * 4 + 0] = to_tf32(Wg[k0 * Dout + n0]);
        sm[OFF_W + idx * 4 + 1] = to_tf32(Wg[(k0 + 4) * Dout + n0]);
        sm[OFF_W + idx * 4 + 2] = to_tf32(Wg[k0 * Dout + n0 + 8]);
        sm[OFF_W + idx * 4 + 3] = to_tf32(Wg[(k0 + 4) * Dout + n0 + 8]);
    }
    if (tid < Dout) sm[OFF_BIAS + tid] = bg[tid];
    __syncthreads();

    float* out_poses = out;
    float* out_c     = out + (size_t)Bsz * Dout;

    const int stride = gridDim.x * 2;
    for (int unit = blockIdx.x * 2 + half; unit < UNITS; unit += stride) {
        const int b0 = unit * 2;

        // ---- stage A (2 batches = 64 rows x 128 cols) into fragment layout ----
        const float4* eg = (const float4*)(embeds + (size_t)b0 * Ncap * Din);
        #pragma unroll
        for (int t = 0; t < 8; t++) {
            int i = htid + t * 256;         // 2048 float4s
            float4 e = eg[i];
            int r    = i >> 5;              // row 0..63
            int j4   = i & 31;
            int rgA  = r >> 5;
            int mt   = (r >> 4) & 1;
            int rr   = r & 15;
            int ks   = j4 >> 1;
            int aidx = (rr >> 3) + ((j4 & 1) << 1);
            int slot = (rgA * 2 + mt) * 16 + ks;
            float* base = As + slot * 132 + (rr & 7) * 16 + aidx;
            base[0]  = to_tf32(e.x);
            base[4]  = to_tf32(e.y);
            base[8]  = to_tf32(e.z);
            base[12] = to_tf32(e.w);
        }
        if (htid < 64)
            scr[S_BIJ + htid] = weights[(size_t)(b0 + (htid >> 5)) * Ncap + (htid & 31)];
        bar_half(half);

        // ---- GEMM: each warp computes 32 rows (rg) x 64 cols (cg) ----
        float c[2][8][4];
        #pragma unroll
        for (int mt = 0; mt < 2; mt++)
            #pragma unroll
            for (int j = 0; j < 8; j++)
                #pragma unroll
                for (int q = 0; q < 4; q++) c[mt][j][q] = 0.0f;

        #pragma unroll
        for (int ks = 0; ks < 16; ks++) {
            float4 a0 = *(const float4*)&As[((rg * 2 + 0) * 16 + ks) * 132 + lane * 4];
            float4 a1 = *(const float4*)&As[((rg * 2 + 1) * 16 + ks) * 132 + lane * 4];
            #pragma unroll
            for (int jp = 0; jp < 4; jp++) {
                float4 b4 = *(const float4*)&sm[OFF_W + (((cg * 4 + jp) * 16 + ks) * 32 + lane) * 4];
                mma_tf32(c[0][2 * jp + 0], a0, b4.x, b4.y);
                mma_tf32(c[1][2 * jp + 0], a1, b4.x, b4.y);
                mma_tf32(c[0][2 * jp + 1], a0, b4.z, b4.w);
                mma_tf32(c[1][2 * jp + 1], a1, b4.z, b4.w);
            }
        }

        // ---- bias add + per-row squared-norm partials ----
        float pn[2][2] = {{0.f, 0.f}, {0.f, 0.f}};
        #pragma unroll
        for (int mt = 0; mt < 2; mt++)
            #pragma unroll
            for (int j = 0; j < 8; j++)
                #pragma unroll
                for (int q = 0; q < 4; q++) {
                    int p = q & 1, h = q >> 1;
                    int col = cg * 64 + j * 8 + qc * 2 + p;
                    float v = c[mt][j][q] + sm[OFF_BIAS + col];
                    c[mt][j][q] = v;
                    pn[mt][h] += v * v;
                }
        #pragma unroll
        for (int mt = 0; mt < 2; mt++)
            #pragma unroll
            for (int h = 0; h < 2; h++) {
                pn[mt][h] += __shfl_xor_sync(0xffffffffu, pn[mt][h], 1);
                pn[mt][h] += __shfl_xor_sync(0xffffffffu, pn[mt][h], 2);
            }
        if (qc == 0) {
            #pragma unroll
            for (int mt = 0; mt < 2; mt++)
                #pragma unroll
                for (int h = 0; h < 2; h++) {
                    int n = mt * 16 + qr + h * 8;
                    scr[S_NRM + rg * 128 + n * 4 + cg] = pn[mt][h];
                }
        }
        bar_half(half);
        if (htid < 64) {
            const float* p = &scr[S_NRM + (htid >> 5) * 128 + (htid & 31) * 4];
            float s   = p[0] + p[1] + p[2] + p[3];
            scr[S_INV + htid] = 1.0f / fmaxf(sqrtf(s), 1e-12f);
        }
        bar_half(half);
        {
            float inv0 = scr[S_INV + rg * 32 + qr];
            float inv1 = scr[S_INV + rg * 32 + qr + 8];
            float inv2 = scr[S_INV + rg * 32 + 16 + qr];
            float inv3 = scr[S_INV + rg * 32 + 16 + qr + 8];
            #pragma unroll
            for (int j = 0; j < 8; j++) {
                c[0][j][0] *= inv0; c[0][j][1] *= inv0;
                c[0][j][2] *= inv1; c[0][j][3] *= inv1;
                c[1][j][0] *= inv2; c[1][j][1] *= inv2;
                c[1][j][2] *= inv3; c[1][j][3] *= inv3;
            }
        }

        // ---- dynamic routing (fragments stay in registers as u_hat) ----
        #pragma unroll 1
        for (int it = 0; it < RITERS; it++) {
            bar_half(half);
            if (cg == 0) {    // warps 0 and 4 of the half
                float bv = scr[S_BIJ + rg * 32 + lane];
                float m = bv;
                #pragma unroll
                for (int off = 16; off; off >>= 1)
                    m = fmaxf(m, __shfl_xor_sync(0xffffffffu, m, off));
                float e = expf(bv - m);
                float ssum = e;
                #pragma unroll
                for (int off = 16; off; off >>= 1)
                    ssum += __shfl_xor_sync(0xffffffffu, ssum, off);
                scr[S_C + rg * 32 + lane] = e * (32.0f / ssum);
            }
            bar_half(half);

            // s[d] = sum_n c[n] * u_hat[n][d], from fragments
            float cv0 = scr[S_C + rg * 32 + qr];
            float cv1 = scr[S_C + rg * 32 + qr + 8];
            float cv2 = scr[S_C + rg * 32 + 16 + qr];
            float cv3 = scr[S_C + rg * 32 + 16 + qr + 8];
            float sp[8][2];
            #pragma unroll
            for (int j = 0; j < 8; j++) {
                sp[j][0] = cv0 * c[0][j][0] + cv1 * c[0][j][2]
                         + cv2 * c[1][j][0] + cv3 * c[1][j][2];
                sp[j][1] = cv0 * c[0][j][1] + cv1 * c[0][j][3]
                         + cv2 * c[1][j][1] + cv3 * c[1][j][3];
            }
            #pragma unroll
            for (int j = 0; j < 8; j++)
                #pragma unroll
                for (int p = 0; p < 2; p++) {
                    sp[j][p] += __shfl_xor_sync(0xffffffffu, sp[j][p], 4);
                    sp[j][p] += __shfl_xor_sync(0xffffffffu, sp[j][p], 8);
                    sp[j][p] += __shfl_xor_sync(0xffffffffu, sp[j][p], 16);
                }

            // warp-partial sum(s^2) over this warp's 64 cols
            float qs = 0.0f;
            #pragma unroll
            for (int j = 0; j < 8; j++)
                qs += sp[j][0] * sp[j][0] + sp[j][1] * sp[j][1];
            qs += __shfl_xor_sync(0xffffffffu, qs, 1);
            qs += __shfl_xor_sync(0xffffffffu, qs, 2);
            if (lane == 0) scr[S_SQP + rg * 4 + cg] = qs;
            bar_half(half);

            float t4 = scr[S_SQP + rg * 4 + 0] + scr[S_SQP + rg * 4 + 1]
                     + scr[S_SQP + rg * 4 + 2] + scr[S_SQP + rg * 4 + 3];
            float scale = t4 / ((1.0f + t4) * sqrtf(t4 + 1e-9f));

            if (it < RITERS - 1) {
                // agree[n] = dot(u_hat[n,:], v) partials, from fragments
                float ap[2][2] = {{0.f, 0.f}, {0.f, 0.f}};
                #pragma unroll
                for (int j = 0; j < 8; j++) {
                    float s0 = sp[j][0], s1 = sp[j][1];
                    ap[0][0] += c[0][j][0] * s0 + c[0][j][1] * s1;
                    ap[0][1] += c[0][j][2] * s0 + c[0][j][3] * s1;
                    ap[1][0] += c[1][j][0] * s0 + c[1][j][1] * s1;
                    ap[1][1] += c[1][j][2] * s0 + c[1][j][3] * s1;
                }
                #pragma unroll
                for (int mt = 0; mt < 2; mt++)
                    #pragma unroll
                    for (int h = 0; h < 2; h++) {
                        float a = ap[mt][h] * scale;
                        a += __shfl_xor_sync(0xffffffffu, a, 1);
                        a += __shfl_xor_sync(0xffffffffu, a, 2);
                        if (qc == 0) {
                            int n = mt * 16 + qr + h * 8;
                            scr[S_AGR + rg * 128 + n * 4 + cg] = a;
                        }
                    }
                bar_half(half);
                if (htid < 64) {
                    const float* p = &scr[S_AGR + (htid >> 5) * 128 + (htid & 31) * 4];
                    scr[S_BIJ + htid] += p[0] + p[1] + p[2] + p[3];
                }
            } else {
                // final iter: stage v into smem for coalesced output
                #pragma unroll
                for (int j = 0; j < 8; j++)
                    if (qr == j) {
                        float2 vv = make_float2(scale * sp[j][0], scale * sp[j][1]);
                        *(float2*)&scr[S_V + rg * 256 + cg * 64 + j * 8 + qc * 2] = vv;
                    }
            }
        }

        bar_half(half);   // v staged; also: all A/scr consumers done before restage
        out_poses[(size_t)b0 * Dout + htid]       = scr[S_V + htid];
        out_poses[(size_t)(b0 + 1) * Dout + htid] = scr[S_V + 256 + htid];
        if (htid < 64)
            out_c[(size_t)(b0 + (htid >> 5)) * Ncap + (htid & 31)] = scr[S_C + htid];
        bar_half(half);   // outputs/scr reads done before next unit overwrites
    }
}

extern "C" void kernel_launch(void* const* d_in, const int* in_sizes, int n_in,
                              void* d_out, int out_size) {
    const float* embeds  = (const float*)d_in[0];
    const float* weights = (const float*)d_in[1];
    const float* Wg      = (const float*)d_in[2];
    const float* bg      = (const float*)d_in[3];
    float* out = (float*)d_out;

    cudaFuncSetAttribute(dyr_agg_kernel,
                         cudaFuncAttributeMaxDynamicSharedMemorySize, SMEM_BYTES);
    int sms = 148;
    cudaDeviceGetAttribute(&sms, cudaDevAttrMultiProcessorCount, 0);
    dyr_agg_kernel<<<sms, 512, SMEM_BYTES>>>(embeds, weights, Wg, bg, out);
}

// round 6
// speedup vs baseline: 1.8740x; 1.0725x over previous
#include <cuda_runtime.h>
#include <cstdint>

namespace {
constexpr int Bsz    = 16384;
constexpr int Ncap   = 32;
constexpr int Din    = 128;
constexpr int Dout   = 256;
constexpr int RITERS = 3;
constexpr int UNITS  = Bsz / 2;

// shared memory layout (float offsets)
// W: 16 jp-groups * 16 ks * 32 lanes * float4 = 32768 floats (131072 B)
constexpr int OFF_W    = 0;
constexpr int OFF_A    = OFF_W + 32768;        // per-half: 64 rows * 132 = 8448 floats; x2
constexpr int OFF_BIAS = OFF_A + 2 * 8448;     // 256
constexpr int OFF_SCR  = OFF_BIAS + 256;       // per-half scratch, 1792 floats each
// scratch offsets within a half
constexpr int S_NRM = 0;      // [2][32][4] = 256
constexpr int S_INV = 256;    // 64
constexpr int S_BIJ = 320;    // 64
constexpr int S_C   = 384;    // 64
constexpr int S_V   = 960;    // 512
constexpr int S_SQP = 1472;   // 16
constexpr int S_AGR = 1492;   // [2][32][4] = 256
constexpr int SCR_SIZE = 1792;
constexpr int SMEM_FLOATS = OFF_SCR + 2 * SCR_SIZE;
constexpr int SMEM_BYTES  = SMEM_FLOATS * 4;   // ~209 KB
}

__device__ __forceinline__ float to_tf32(float x) {
    float y;
    asm("cvt.rna.tf32.f32 %0, %1;" : "=f"(y) : "f"(x));
    return y;
}

__device__ __forceinline__ void bar_half(int half) {
    asm volatile("bar.sync %0, 256;" :: "r"(1 + half) : "memory");
}

__device__ __forceinline__ void cp_async16(uint32_t saddr, const void* gptr) {
    asm volatile("cp.async.cg.shared.global [%0], [%1], 16;\n"
                 :: "r"(saddr), "l"(gptr));
}
__device__ __forceinline__ void cp_commit() {
    asm volatile("cp.async.commit_group;\n" ::: "memory");
}
__device__ __forceinline__ void cp_wait0() {
    asm volatile("cp.async.wait_group 0;\n" ::: "memory");
}

__device__ __forceinline__ void mma_tf32(float* c, const float* a, float b0, float b1) {
    asm volatile(
        "mma.sync.aligned.m16n8k8.row.col.f32.tf32.tf32.f32 "
        "{%0,%1,%2,%3}, {%4,%5,%6,%7}, {%8,%9}, {%0,%1,%2,%3};\n"
        : "+f"(c[0]), "+f"(c[1]), "+f"(c[2]), "+f"(c[3])
        : "r"(__float_as_uint(a[0])), "r"(__float_as_uint(a[1])),
          "r"(__float_as_uint(a[2])), "r"(__float_as_uint(a[3])),
          "r"(__float_as_uint(b0)), "r"(__float_as_uint(b1)));
}

__global__ void __launch_bounds__(512, 1)
dyr_agg_kernel(const float* __restrict__ embeds,
               const float* __restrict__ weights,
               const float* __restrict__ Wg,
               const float* __restrict__ bg,
               float* __restrict__ out)
{
    extern __shared__ float sm[];
    const int tid  = threadIdx.x;
    const int half = tid >> 8;       // 0 or 1: independent 256-thread worker
    const int htid = tid & 255;
    const int lane = tid & 31;
    const int wh   = (tid >> 5) & 7; // warp-in-half 0..7
    const int cg   = wh & 3;         // column group: 64 cols at cg*64
    const int rg   = wh >> 2;        // which batch of the pair
    const int qr   = lane >> 2;      // 0..7
    const int qc   = lane & 3;       // 0..3

    float* scr = sm + OFF_SCR + half * SCR_SIZE;
    float* As  = sm + OFF_A + half * 8448;
    const uint32_t As_u32 = (uint32_t)__cvta_generic_to_shared(As);

    // ---- issue async copy of this half's FIRST unit (overlaps W staging) ----
    int unit0 = blockIdx.x * 2 + half;
    {
        // each thread copies 8 x 16B: float4 index i = htid + t*256
        if (unit0 < UNITS) {
            const float4* eg = (const float4*)(embeds + (size_t)unit0 * 2 * Ncap * Din);
            #pragma unroll
            for (int t = 0; t < 8; t++) {
                int i   = htid + t * 256;
                int row = i >> 5, j4 = i & 31;
                cp_async16(As_u32 + (row * 132 + j4 * 4) * 4, eg + i);
            }
        }
        cp_commit();
    }

    // ---- stage W (paired-j layout) + bias, whole CTA, once ----
    // slot (nt2, ks, ln): float4 = {W[k0][n0], W[k0+4][n0], W[k0][n1], W[k0+4][n1]}
    for (int idx = tid; idx < 16 * 16 * 32; idx += 512) {
        int nt2 = idx >> 9;
        int ks  = (idx >> 5) & 15;
        int ln  = idx & 31;
        int k0  = ks * 8 + (ln & 3);
        int n0  = nt2 * 16 + (ln >> 2);
        sm[OFF_W + idx * 4 + 0] = to_tf32(Wg[k0 * Dout + n0]);
        sm[OFF_W + idx * 4 + 1] = to_tf32(Wg[(k0 + 4) * Dout + n0]);
        sm[OFF_W + idx * 4 + 2] = to_tf32(Wg[k0 * Dout + n0 + 8]);
        sm[OFF_W + idx * 4 + 3] = to_tf32(Wg[(k0 + 4) * Dout + n0 + 8]);
    }
    if (tid < Dout) sm[OFF_BIAS + tid] = bg[tid];
    __syncthreads();

    float* out_poses = out;
    float* out_c     = out + (size_t)Bsz * Dout;

    const int stride = gridDim.x * 2;
    for (int unit = unit0; unit < UNITS; unit += stride) {
        const int  b0       = unit * 2;
        const int  nunit    = unit + stride;
        const bool has_next = nunit < UNITS;

        if (htid < 64)
            scr[S_BIJ + htid] = weights[(size_t)(b0 + (htid >> 5)) * Ncap + (htid & 31)];

        // A copy for this unit was issued last iteration (or prologue)
        cp_wait0();
        bar_half(half);   // A visible to all warps of this half

        // ---- GEMM: each warp computes 32 rows (rg) x 64 cols (cg) ----
        float c[2][8][4];
        #pragma unroll
        for (int mt = 0; mt < 2; mt++)
            #pragma unroll
            for (int j = 0; j < 8; j++)
                #pragma unroll
                for (int q = 0; q < 4; q++) c[mt][j][q] = 0.0f;

        #pragma unroll
        for (int ks = 0; ks < 16; ks++) {
            float a[2][4];
            #pragma unroll
            for (int mt = 0; mt < 2; mt++) {
                const float* ar = As + (rg * 32 + mt * 16) * 132 + ks * 8 + qc;
                a[mt][0] = to_tf32(ar[qr * 132]);
                a[mt][1] = to_tf32(ar[(qr + 8) * 132]);
                a[mt][2] = to_tf32(ar[qr * 132 + 4]);
                a[mt][3] = to_tf32(ar[(qr + 8) * 132 + 4]);
            }
            #pragma unroll
            for (int jp = 0; jp < 4; jp++) {
                float4 b4 = *(const float4*)&sm[OFF_W + (((cg * 4 + jp) * 16 + ks) * 32 + lane) * 4];
                mma_tf32(c[0][2 * jp + 0], a[0], b4.x, b4.y);
                mma_tf32(c[1][2 * jp + 0], a[1], b4.x, b4.y);
                mma_tf32(c[0][2 * jp + 1], a[0], b4.z, b4.w);
                mma_tf32(c[1][2 * jp + 1], a[1], b4.z, b4.w);
            }
        }

        // ---- bias add + per-row squared-norm partials ----
        float pn[2][2] = {{0.f, 0.f}, {0.f, 0.f}};
        #pragma unroll
        for (int mt = 0; mt < 2; mt++)
            #pragma unroll
            for (int j = 0; j < 8; j++)
                #pragma unroll
                for (int q = 0; q < 4; q++) {
                    int p = q & 1, h = q >> 1;
                    int col = cg * 64 + j * 8 + qc * 2 + p;
                    float v = c[mt][j][q] + sm[OFF_BIAS + col];
                    c[mt][j][q] = v;
                    pn[mt][h] += v * v;
                }
        #pragma unroll
        for (int mt = 0; mt < 2; mt++)
            #pragma unroll
            for (int h = 0; h < 2; h++) {
                pn[mt][h] += __shfl_xor_sync(0xffffffffu, pn[mt][h], 1);
                pn[mt][h] += __shfl_xor_sync(0xffffffffu, pn[mt][h], 2);
            }
        if (qc == 0) {
            #pragma unroll
            for (int mt = 0; mt < 2; mt++)
                #pragma unroll
                for (int h = 0; h < 2; h++) {
                    int n = mt * 16 + qr + h * 8;
                    scr[S_NRM + rg * 128 + n * 4 + cg] = pn[mt][h];
                }
        }
        bar_half(half);   // GEMM reads of A done; norm partials visible

        // ---- A buffer now dead: issue next unit's async copy (overlaps routing) ----
        if (has_next) {
            const float4* eg = (const float4*)(embeds + (size_t)nunit * 2 * Ncap * Din);
            #pragma unroll
            for (int t = 0; t < 8; t++) {
                int i   = htid + t * 256;
                int row = i >> 5, j4 = i & 31;
                cp_async16(As_u32 + (row * 132 + j4 * 4) * 4, eg + i);
            }
        }
        cp_commit();

        if (htid < 64) {
            const float* p = &scr[S_NRM + (htid >> 5) * 128 + (htid & 31) * 4];
            float s = p[0] + p[1] + p[2] + p[3];
            scr[S_INV + htid] = 1.0f / fmaxf(sqrtf(s), 1e-12f);
        }
        bar_half(half);
        {
            float inv0 = scr[S_INV + rg * 32 + qr];
            float inv1 = scr[S_INV + rg * 32 + qr + 8];
            float inv2 = scr[S_INV + rg * 32 + 16 + qr];
            float inv3 = scr[S_INV + rg * 32 + 16 + qr + 8];
            #pragma unroll
            for (int j = 0; j < 8; j++) {
                c[0][j][0] *= inv0; c[0][j][1] *= inv0;
                c[0][j][2] *= inv1; c[0][j][3] *= inv1;
                c[1][j][0] *= inv2; c[1][j][1] *= inv2;
                c[1][j][2] *= inv3; c[1][j][3] *= inv3;
            }
        }

        // ---- dynamic routing (fragments stay in registers as u_hat) ----
        #pragma unroll 1
        for (int it = 0; it < RITERS; it++) {
            bar_half(half);
            if (cg == 0) {    // warps 0 and 4 of the half
                float bv = scr[S_BIJ + rg * 32 + lane];
                float m = bv;
                #pragma unroll
                for (int off = 16; off; off >>= 1)
                    m = fmaxf(m, __shfl_xor_sync(0xffffffffu, m, off));
                float e = expf(bv - m);
                float ssum = e;
                #pragma unroll
                for (int off = 16; off; off >>= 1)
                    ssum += __shfl_xor_sync(0xffffffffu, ssum, off);
                scr[S_C + rg * 32 + lane] = e * (32.0f / ssum);
            }
            bar_half(half);

            // s[d] = sum_n c[n] * u_hat[n][d], from fragments
            float cv0 = scr[S_C + rg * 32 + qr];
            float cv1 = scr[S_C + rg * 32 + qr + 8];
            float cv2 = scr[S_C + rg * 32 + 16 + qr];
            float cv3 = scr[S_C + rg * 32 + 16 + qr + 8];
            float sp[8][2];
            #pragma unroll
            for (int j = 0; j < 8; j++) {
                sp[j][0] = cv0 * c[0][j][0] + cv1 * c[0][j][2]
                         + cv2 * c[1][j][0] + cv3 * c[1][j][2];
                sp[j][1] = cv0 * c[0][j][1] + cv1 * c[0][j][3]
                         + cv2 * c[1][j][1] + cv3 * c[1][j][3];
            }
            #pragma unroll
            for (int j = 0; j < 8; j++)
                #pragma unroll
                for (int p = 0; p < 2; p++) {
                    sp[j][p] += __shfl_xor_sync(0xffffffffu, sp[j][p], 4);
                    sp[j][p] += __shfl_xor_sync(0xffffffffu, sp[j][p], 8);
                    sp[j][p] += __shfl_xor_sync(0xffffffffu, sp[j][p], 16);
                }

            // warp-partial sum(s^2) over this warp's 64 cols
            float qs = 0.0f;
            #pragma unroll
            for (int j = 0; j < 8; j++)
                qs += sp[j][0] * sp[j][0] + sp[j][1] * sp[j][1];
            qs += __shfl_xor_sync(0xffffffffu, qs, 1);
            qs += __shfl_xor_sync(0xffffffffu, qs, 2);
            if (lane == 0) scr[S_SQP + rg * 4 + cg] = qs;
            bar_half(half);

            float t4 = scr[S_SQP + rg * 4 + 0] + scr[S_SQP + rg * 4 + 1]
                     + scr[S_SQP + rg * 4 + 2] + scr[S_SQP + rg * 4 + 3];
            float scale = t4 / ((1.0f + t4) * sqrtf(t4 + 1e-9f));

            if (it < RITERS - 1) {
                // agree[n] = dot(u_hat[n,:], v) partials, from fragments
                float ap[2][2] = {{0.f, 0.f}, {0.f, 0.f}};
                #pragma unroll
                for (int j = 0; j < 8; j++) {
                    float s0 = sp[j][0], s1 = sp[j][1];
                    ap[0][0] += c[0][j][0] * s0 + c[0][j][1] * s1;
                    ap[0][1] += c[0][j][2] * s0 + c[0][j][3] * s1;
                    ap[1][0] += c[1][j][0] * s0 + c[1][j][1] * s1;
                    ap[1][1] += c[1][j][2] * s0 + c[1][j][3] * s1;
                }
                #pragma unroll
                for (int mt = 0; mt < 2; mt++)
                    #pragma unroll
                    for (int h = 0; h < 2; h++) {
                        float a = ap[mt][h] * scale;
                        a += __shfl_xor_sync(0xffffffffu, a, 1);
                        a += __shfl_xor_sync(0xffffffffu, a, 2);
                        if (qc == 0) {
                            int n = mt * 16 + qr + h * 8;
                            scr[S_AGR + rg * 128 + n * 4 + cg] = a;
                        }
                    }
                bar_half(half);
                if (htid < 64) {
                    const float* p = &scr[S_AGR + (htid >> 5) * 128 + (htid & 31) * 4];
                    scr[S_BIJ + htid] += p[0] + p[1] + p[2] + p[3];
                }
            } else {
                // final iter: stage v into smem for coalesced output
                #pragma unroll
                for (int j = 0; j < 8; j++)
                    if (qr == j) {
                        float2 vv = make_float2(scale * sp[j][0], scale * sp[j][1]);
                        *(float2*)&scr[S_V + rg * 256 + cg * 64 + j * 8 + qc * 2] = vv;
                    }
            }
        }

        bar_half(half);   // v staged; scr consumers done
        out_poses[(size_t)b0 * Dout + htid]       = scr[S_V + htid];
        out_poses[(size_t)(b0 + 1) * Dout + htid] = scr[S_V + 256 + htid];
        if (htid < 64)
            out_c[(size_t)(b0 + (htid >> 5)) * Ncap + (htid & 31)] = scr[S_C + htid];
        bar_half(half);   // outputs/scr reads done before next unit overwrites
    }
}

extern "C" void kernel_launch(void* const* d_in, const int* in_sizes, int n_in,
                              void* d_out, int out_size) {
    const float* embeds  = (const float*)d_in[0];
    const float* weights = (const float*)d_in[1];
    const float* Wg      = (const float*)d_in[2];
    const float* bg      = (const float*)d_in[3];
    float* out = (float*)d_out;

    cudaFuncSetAttribute(dyr_agg_kernel,
                         cudaFuncAttributeMaxDynamicSharedMemorySize, SMEM_BYTES);
    int sms = 148;
    cudaDeviceGetAttribute(&sms, cudaDevAttrMultiProcessorCount, 0);
    dyr_agg_kernel<<<sms, 512, SMEM_BYTES>>>(embeds, weights, Wg, bg, out);
}

// round 7
// speedup vs baseline: 1.9304x; 1.0301x over previous
#include <cuda_runtime.h>
#include <cstdint>

namespace {
constexpr int Bsz    = 16384;
constexpr int Ncap   = 32;
constexpr int Din    = 128;
constexpr int Dout   = 256;
constexpr int RITERS = 3;
constexpr int UNITS  = Bsz / 2;

// shared memory layout (float offsets)
// W: 16 jp-groups * 16 ks * 32 lanes * float4 = 32768 floats (131072 B)
constexpr int OFF_W    = 0;
constexpr int OFF_A    = OFF_W + 32768;        // per-half: 64 rows * 132 = 8448 floats; x2
constexpr int OFF_BIAS = OFF_A + 2 * 8448;     // 256
constexpr int OFF_SCR  = OFF_BIAS + 256;       // per-half scratch
// scratch offsets within a half
constexpr int S_NRM  = 0;      // [2][32][4] = 256
constexpr int S_INV  = 256;    // 64
constexpr int S_BIJ0 = 320;    // 64  (b_ij slot 0)
constexpr int S_C    = 384;    // 64
constexpr int S_V    = 960;    // 512
constexpr int S_SQP  = 1472;   // 16
constexpr int S_AGR  = 1492;   // [2][32][4] = 256
constexpr int S_BIJ1 = 1748;   // 64  (b_ij slot 1)
constexpr int SCR_SIZE = 1812;
constexpr int SMEM_FLOATS = OFF_SCR + 2 * SCR_SIZE;
constexpr int SMEM_BYTES  = SMEM_FLOATS * 4;   // ~214 KB
}

__device__ __forceinline__ float to_tf32(float x) {
    float y;
    asm("cvt.rna.tf32.f32 %0, %1;" : "=f"(y) : "f"(x));
    return y;
}

__device__ __forceinline__ void bar_half(int half) {
    asm volatile("bar.sync %0, 256;" :: "r"(1 + half) : "memory");
}

__device__ __forceinline__ void cp_async16(uint32_t saddr, const void* gptr) {
    asm volatile("cp.async.cg.shared.global [%0], [%1], 16;\n"
                 :: "r"(saddr), "l"(gptr));
}
__device__ __forceinline__ void cp_commit() {
    asm volatile("cp.async.commit_group;\n" ::: "memory");
}
__device__ __forceinline__ void cp_wait0() {
    asm volatile("cp.async.wait_group 0;\n" ::: "memory");
}

// A operand registers carry raw fp32 bits; tf32 MMA reads bits[31:13] (RZ).
__device__ __forceinline__ void mma_tf32(float* c, const float* a, float b0, float b1) {
    asm volatile(
        "mma.sync.aligned.m16n8k8.row.col.f32.tf32.tf32.f32 "
        "{%0,%1,%2,%3}, {%4,%5,%6,%7}, {%8,%9}, {%0,%1,%2,%3};\n"
        : "+f"(c[0]), "+f"(c[1]), "+f"(c[2]), "+f"(c[3])
        : "r"(__float_as_uint(a[0])), "r"(__float_as_uint(a[1])),
          "r"(__float_as_uint(a[2])), "r"(__float_as_uint(a[3])),
          "r"(__float_as_uint(b0)), "r"(__float_as_uint(b1)));
}

__global__ void __launch_bounds__(512, 1)
dyr_agg_kernel(const float* __restrict__ embeds,
               const float* __restrict__ weights,
               const float* __restrict__ Wg,
               const float* __restrict__ bg,
               float* __restrict__ out)
{
    extern __shared__ float sm[];
    const int tid  = threadIdx.x;
    const int half = tid >> 8;       // 0 or 1: independent 256-thread worker
    const int htid = tid & 255;
    const int lane = tid & 31;
    const int wh   = (tid >> 5) & 7; // warp-in-half 0..7
    const int cg   = wh & 3;         // column group: 64 cols at cg*64
    const int rg   = wh >> 2;        // which batch of the pair
    const int qr   = lane >> 2;      // 0..7
    const int qc   = lane & 3;       // 0..3

    float* scr = sm + OFF_SCR + half * SCR_SIZE;
    float* As  = sm + OFF_A + half * 8448;
    const uint32_t As_u32  = (uint32_t)__cvta_generic_to_shared(As);
    const uint32_t scr_u32 = (uint32_t)__cvta_generic_to_shared(scr);

    // ---- issue async copy of this half's FIRST unit (overlaps W staging) ----
    int unit0 = blockIdx.x * 2 + half;
    if (unit0 < UNITS) {
        const float4* eg = (const float4*)(embeds + (size_t)unit0 * 2 * Ncap * Din);
        #pragma unroll
        for (int t = 0; t < 8; t++) {
            int i   = htid + t * 256;
            int row = i >> 5, j4 = i & 31;
            cp_async16(As_u32 + (row * 132 + j4 * 4) * 4, eg + i);
        }
        if (htid < 16)   // 64 floats of routing logits -> slot 0
            cp_async16(scr_u32 + (S_BIJ0 + htid * 4) * 4,
                       weights + (size_t)unit0 * 64 + htid * 4);
    }
    cp_commit();

    // ---- stage W (paired-j layout) + bias, whole CTA, once ----
    for (int idx = tid; idx < 16 * 16 * 32; idx += 512) {
        int nt2 = idx >> 9;
        int ks  = (idx >> 5) & 15;
        int ln  = idx & 31;
        int k0  = ks * 8 + (ln & 3);
        int n0  = nt2 * 16 + (ln >> 2);
        sm[OFF_W + idx * 4 + 0] = to_tf32(Wg[k0 * Dout + n0]);
        sm[OFF_W + idx * 4 + 1] = to_tf32(Wg[(k0 + 4) * Dout + n0]);
        sm[OFF_W + idx * 4 + 2] = to_tf32(Wg[k0 * Dout + n0 + 8]);
        sm[OFF_W + idx * 4 + 3] = to_tf32(Wg[(k0 + 4) * Dout + n0 + 8]);
    }
    if (tid < Dout) sm[OFF_BIAS + tid] = bg[tid];
    __syncthreads();

    float* out_poses = out;
    float* out_c     = out + (size_t)Bsz * Dout;

    const int stride = gridDim.x * 2;
    int p = 0;  // b_ij slot parity (per loop iteration)
    for (int unit = unit0; unit < UNITS; unit += stride, p ^= 1) {
        const int  b0       = unit * 2;
        const int  nunit    = unit + stride;
        const bool has_next = nunit < UNITS;
        const int  BIJ      = p ? S_BIJ1 : S_BIJ0;
        const int  BIJN     = p ? S_BIJ0 : S_BIJ1;

        // A + b_ij for this unit were issued last iteration (or prologue)
        cp_wait0();
        bar_half(half);   // visible to all warps of this half

        // ---- GEMM: each warp computes 32 rows (rg) x 64 cols (cg) ----
        float c[2][8][4];
        #pragma unroll
        for (int mt = 0; mt < 2; mt++)
            #pragma unroll
            for (int j = 0; j < 8; j++)
                #pragma unroll
                for (int q = 0; q < 4; q++) c[mt][j][q] = 0.0f;

        #pragma unroll
        for (int ks = 0; ks < 16; ks++) {
            float a[2][4];
            #pragma unroll
            for (int mt = 0; mt < 2; mt++) {
                const float* ar = As + (rg * 32 + mt * 16) * 132 + ks * 8 + qc;
                a[mt][0] = ar[qr * 132];
                a[mt][1] = ar[(qr + 8) * 132];
                a[mt][2] = ar[qr * 132 + 4];
                a[mt][3] = ar[(qr + 8) * 132 + 4];
            }
            #pragma unroll
            for (int jp = 0; jp < 4; jp++) {
                float4 b4 = *(const float4*)&sm[OFF_W + (((cg * 4 + jp) * 16 + ks) * 32 + lane) * 4];
                mma_tf32(c[0][2 * jp + 0], a[0], b4.x, b4.y);
                mma_tf32(c[1][2 * jp + 0], a[1], b4.x, b4.y);
                mma_tf32(c[0][2 * jp + 1], a[0], b4.z, b4.w);
                mma_tf32(c[1][2 * jp + 1], a[1], b4.z, b4.w);
            }
        }

        // ---- bias add + per-row squared-norm partials ----
        float pn[2][2] = {{0.f, 0.f}, {0.f, 0.f}};
        #pragma unroll
        for (int mt = 0; mt < 2; mt++)
            #pragma unroll
            for (int j = 0; j < 8; j++)
                #pragma unroll
                for (int q = 0; q < 4; q++) {
                    int pq = q & 1, h = q >> 1;
                    int col = cg * 64 + j * 8 + qc * 2 + pq;
                    float v = c[mt][j][q] + sm[OFF_BIAS + col];
                    c[mt][j][q] = v;
                    pn[mt][h] += v * v;
                }
        #pragma unroll
        for (int mt = 0; mt < 2; mt++)
            #pragma unroll
            for (int h = 0; h < 2; h++) {
                pn[mt][h] += __shfl_xor_sync(0xffffffffu, pn[mt][h], 1);
                pn[mt][h] += __shfl_xor_sync(0xffffffffu, pn[mt][h], 2);
            }
        if (qc == 0) {
            #pragma unroll
            for (int mt = 0; mt < 2; mt++)
                #pragma unroll
                for (int h = 0; h < 2; h++) {
                    int n = mt * 16 + qr + h * 8;
                    scr[S_NRM + rg * 128 + n * 4 + cg] = pn[mt][h];
                }
        }
        bar_half(half);   // GEMM reads of A done; norm partials visible

        // ---- A buffer now dead: issue next unit's async copies (overlap routing) ----
        if (has_next) {
            const float4* eg = (const float4*)(embeds + (size_t)nunit * 2 * Ncap * Din);
            #pragma unroll
            for (int t = 0; t < 8; t++) {
                int i   = htid + t * 256;
                int row = i >> 5, j4 = i & 31;
                cp_async16(As_u32 + (row * 132 + j4 * 4) * 4, eg + i);
            }
            if (htid < 16)
                cp_async16(scr_u32 + (BIJN + htid * 4) * 4,
                           weights + (size_t)nunit * 64 + htid * 4);
        }
        cp_commit();

        if (htid < 64) {
            const float* pr = &scr[S_NRM + (htid >> 5) * 128 + (htid & 31) * 4];
            float s = pr[0] + pr[1] + pr[2] + pr[3];
            scr[S_INV + htid] = 1.0f / fmaxf(sqrtf(s), 1e-12f);
        }
        bar_half(half);
        {
            float inv0 = scr[S_INV + rg * 32 + qr];
            float inv1 = scr[S_INV + rg * 32 + qr + 8];
            float inv2 = scr[S_INV + rg * 32 + 16 + qr];
            float inv3 = scr[S_INV + rg * 32 + 16 + qr + 8];
            #pragma unroll
            for (int j = 0; j < 8; j++) {
                c[0][j][0] *= inv0; c[0][j][1] *= inv0;
                c[0][j][2] *= inv1; c[0][j][3] *= inv1;
                c[1][j][0] *= inv2; c[1][j][1] *= inv2;
                c[1][j][2] *= inv3; c[1][j][3] *= inv3;
            }
        }

        // ---- dynamic routing (fragments stay in registers as u_hat) ----
        #pragma unroll 1
        for (int it = 0; it < RITERS; it++) {
            bar_half(half);
            if (cg == 0) {    // warps 0 and 4 of the half
                float bv = scr[BIJ + rg * 32 + lane];
                float m = bv;
                #pragma unroll
                for (int off = 16; off; off >>= 1)
                    m = fmaxf(m, __shfl_xor_sync(0xffffffffu, m, off));
                float e = expf(bv - m);
                float ssum = e;
                #pragma unroll
                for (int off = 16; off; off >>= 1)
                    ssum += __shfl_xor_sync(0xffffffffu, ssum, off);
                scr[S_C + rg * 32 + lane] = e * (32.0f / ssum);
            }
            bar_half(half);

            // s[d] = sum_n c[n] * u_hat[n][d], from fragments
            float cv0 = scr[S_C + rg * 32 + qr];
            float cv1 = scr[S_C + rg * 32 + qr + 8];
            float cv2 = scr[S_C + rg * 32 + 16 + qr];
            float cv3 = scr[S_C + rg * 32 + 16 + qr + 8];
            float sp[8][2];
            #pragma unroll
            for (int j = 0; j < 8; j++) {
                sp[j][0] = cv0 * c[0][j][0] + cv1 * c[0][j][2]
                         + cv2 * c[1][j][0] + cv3 * c[1][j][2];
                sp[j][1] = cv0 * c[0][j][1] + cv1 * c[0][j][3]
                         + cv2 * c[1][j][1] + cv3 * c[1][j][3];
            }
            #pragma unroll
            for (int j = 0; j < 8; j++)
                #pragma unroll
                for (int pp = 0; pp < 2; pp++) {
                    sp[j][pp] += __shfl_xor_sync(0xffffffffu, sp[j][pp], 4);
                    sp[j][pp] += __shfl_xor_sync(0xffffffffu, sp[j][pp], 8);
                    sp[j][pp] += __shfl_xor_sync(0xffffffffu, sp[j][pp], 16);
                }

            // warp-partial sum(s^2) over this warp's 64 cols
            float qs = 0.0f;
            #pragma unroll
            for (int j = 0; j < 8; j++)
                qs += sp[j][0] * sp[j][0] + sp[j][1] * sp[j][1];
            qs += __shfl_xor_sync(0xffffffffu, qs, 1);
            qs += __shfl_xor_sync(0xffffffffu, qs, 2);
            if (lane == 0) scr[S_SQP + rg * 4 + cg] = qs;
            bar_half(half);

            float t4 = scr[S_SQP + rg * 4 + 0] + scr[S_SQP + rg * 4 + 1]
                     + scr[S_SQP + rg * 4 + 2] + scr[S_SQP + rg * 4 + 3];
            float scale = t4 / ((1.0f + t4) * sqrtf(t4 + 1e-9f));

            if (it < RITERS - 1) {
                // agree[n] = dot(u_hat[n,:], v) partials, from fragments
                float ap[2][2] = {{0.f, 0.f}, {0.f, 0.f}};
                #pragma unroll
                for (int j = 0; j < 8; j++) {
                    float s0 = sp[j][0], s1 = sp[j][1];
                    ap[0][0] += c[0][j][0] * s0 + c[0][j][1] * s1;
                    ap[0][1] += c[0][j][2] * s0 + c[0][j][3] * s1;
                    ap[1][0] += c[1][j][0] * s0 + c[1][j][1] * s1;
                    ap[1][1] += c[1][j][2] * s0 + c[1][j][3] * s1;
                }
                #pragma unroll
                for (int mt = 0; mt < 2; mt++)
                    #pragma unroll
                    for (int h = 0; h < 2; h++) {
                        float a = ap[mt][h] * scale;
                        a += __shfl_xor_sync(0xffffffffu, a, 1);
                        a += __shfl_xor_sync(0xffffffffu, a, 2);
                        if (qc == 0) {
                            int n = mt * 16 + qr + h * 8;
                            scr[S_AGR + rg * 128 + n * 4 + cg] = a;
                        }
                    }
                bar_half(half);
                if (htid < 64) {
                    const float* pr = &scr[S_AGR + (htid >> 5) * 128 + (htid & 31) * 4];
                    scr[BIJ + htid] += pr[0] + pr[1] + pr[2] + pr[3];
                }
            } else {
                // final iter: stage v into smem for coalesced output
                #pragma unroll
                for (int j = 0; j < 8; j++)
                    if (qr == j) {
                        float2 vv = make_float2(scale * sp[j][0], scale * sp[j][1]);
                        *(float2*)&scr[S_V + rg * 256 + cg * 64 + j * 8 + qc * 2] = vv;
                    }
            }
        }

        bar_half(half);   // v staged; scr consumers done
        out_poses[(size_t)b0 * Dout + htid]       = scr[S_V + htid];
        out_poses[(size_t)(b0 + 1) * Dout + htid] = scr[S_V + 256 + htid];
        if (htid < 64)
            out_c[(size_t)(b0 + (htid >> 5)) * Ncap + (htid & 31)] = scr[S_C + htid];
        bar_half(half);   // outputs/scr reads done before next unit overwrites
    }
}

extern "C" void kernel_launch(void* const* d_in, const int* in_sizes, int n_in,
                              void* d_out, int out_size) {
    const float* embeds  = (const float*)d_in[0];
    const float* weights = (const float*)d_in[1];
    const float* Wg      = (const float*)d_in[2];
    const float* bg      = (const float*)d_in[3];
    float* out = (float*)d_out;

    cudaFuncSetAttribute(dyr_agg_kernel,
                         cudaFuncAttributeMaxDynamicSharedMemorySize, SMEM_BYTES);
    int sms = 148;
    cudaDeviceGetAttribute(&sms, cudaDevAttrMultiProcessorCount, 0);
    dyr_agg_kernel<<<sms, 512, SMEM_BYTES>>>(embeds, weights, Wg, bg, out);
}